// round 6
// baseline (speedup 1.0000x reference)
#include <cuda_runtime.h>

// ---------------------------------------------------------------------------
// GIN graph network, fp32, multi-kernel. N=100000 nodes, E=1.25M edges, D=64,
// L=4 layers, B=2048 graphs. Output = [node_repr (N*64) | graph_repr (B*64)].
// ---------------------------------------------------------------------------

#define MAXN 100000
#define MAXE 1250000
#define MAXB 2048

__device__ __align__(16) float g_h[(size_t)MAXN * 64];
__device__ __align__(16) float g_agg[(size_t)MAXN * 64];   // also reused as y2
__device__ __align__(16) float g_y1[(size_t)MAXN * 128];
__device__ __align__(16) float g_stats[384];  // [0:128) sum1 [128:256) sq1 [256:320) sum2 [320:384) sq2
__device__ __align__(16) float g_bn1[256];    // scale1[128], shift1[128]
__device__ __align__(16) float g_bn2[128];    // scale2[64], shift2[64]
__device__ float g_cnt[MAXB];

__device__ __forceinline__ void red_add_v4(float* addr, float4 v) {
    asm volatile("red.global.add.v4.f32 [%0], {%1,%2,%3,%4};"
                 :: "l"(addr), "f"(v.x), "f"(v.y), "f"(v.z), "f"(v.w)
                 : "memory");
}

// ---------------------------------------------------------------------------
// Atom encoder: h[n,:] = sum_f atom_emb[f, x_feat[n,f], :]
// One thread per (node, float4-chunk).
// ---------------------------------------------------------------------------
__global__ __launch_bounds__(256) void atom_kernel(
    const float* __restrict__ atom_emb, const int* __restrict__ x_feat, int n)
{
    int wi = blockIdx.x * 256 + threadIdx.x;
    int nid = wi >> 4;
    if (nid >= n) return;
    int c = wi & 15;
    const float4* ae = (const float4*)atom_emb;  // [9,128,16] float4
    float4 acc = make_float4(0.f, 0.f, 0.f, 0.f);
#pragma unroll
    for (int f = 0; f < 9; f++) {
        int idx = __ldg(&x_feat[nid * 9 + f]);
        float4 v = ae[(f * 128 + idx) * 16 + c];
        acc.x += v.x; acc.y += v.y; acc.z += v.z; acc.w += v.w;
    }
    ((float4*)g_h)[(size_t)nid * 16 + c] = acc;
}

// ---------------------------------------------------------------------------
// Clear helpers
// ---------------------------------------------------------------------------
__global__ __launch_bounds__(256) void clear_agg_kernel(int count4)  // n*16 float4
{
    int i = blockIdx.x * 256 + threadIdx.x;
    if (i < count4) ((float4*)g_agg)[i] = make_float4(0.f, 0.f, 0.f, 0.f);
}

__global__ void clear_stats_kernel()
{
    int i = threadIdx.x;
    if (i < 384) g_stats[i] = 0.f;
}

__global__ __launch_bounds__(256) void clear_pool_kernel(float* __restrict__ gout, int b)
{
    int i = blockIdx.x * 256 + threadIdx.x;
    if (i < b * 64) gout[i] = 0.f;
    if (i < b) g_cnt[i] = 0.f;
}

// ---------------------------------------------------------------------------
// Edge kernel: msg = relu(h[src] + bond_emb_sum); red-add into agg[dst].
// 16 lanes per edge (float4 chunks). Edge metadata loaded by one lane per
// 16-lane group and shuffled.
// ---------------------------------------------------------------------------
__global__ __launch_bounds__(256) void edge_kernel(
    const float* __restrict__ bond_emb_l,   // [3,8,64] for this layer
    const int* __restrict__ edge_index,     // [2,E]
    const int* __restrict__ edge_attr,      // [E,3]
    int e)
{
    __shared__ float bemb[1536];
    for (int i = threadIdx.x; i < 1536; i += 256) bemb[i] = bond_emb_l[i];
    __syncthreads();

    long long wi = (long long)blockIdx.x * 256 + threadIdx.x;
    int eidx = (int)(wi >> 4);
    int c = threadIdx.x & 15;
    bool valid = eidx < e;

    int src = 0, dst = 0, a0 = 0, a1 = 0, a2 = 0;
    if (valid && c == 0) {
        src = edge_index[eidx];
        dst = edge_index[e + eidx];
        a0 = edge_attr[3 * eidx + 0];
        a1 = edge_attr[3 * eidx + 1];
        a2 = edge_attr[3 * eidx + 2];
    }
    int lane = threadIdx.x & 31;
    int leader = lane & 16;
    src = __shfl_sync(0xffffffffu, src, leader);
    dst = __shfl_sync(0xffffffffu, dst, leader);
    a0  = __shfl_sync(0xffffffffu, a0, leader);
    a1  = __shfl_sync(0xffffffffu, a1, leader);
    a2  = __shfl_sync(0xffffffffu, a2, leader);
    if (!valid) return;

    const float4* b4 = (const float4*)bemb;   // [3,8,16] float4
    float4 e0 = b4[a0 * 16 + c];
    float4 e1 = b4[(8 + a1) * 16 + c];
    float4 e2 = b4[(16 + a2) * 16 + c];
    float4 hv = ((const float4*)g_h)[(size_t)src * 16 + c];
    float4 m;
    m.x = fmaxf(hv.x + e0.x + e1.x + e2.x, 0.f);
    m.y = fmaxf(hv.y + e0.y + e1.y + e2.y, 0.f);
    m.z = fmaxf(hv.z + e0.z + e1.z + e2.z, 0.f);
    m.w = fmaxf(hv.w + e0.w + e1.w + e2.w, 0.f);
    red_add_v4(g_agg + (size_t)dst * 64 + c * 4, m);
}

// ---------------------------------------------------------------------------
// GEMM1: z = (1+eps)*h + agg (64) -> y1 = z@W1 + b1 (128), accumulate BN stats.
// blockDim 128: cg = tid%32 (4 cols), rg = tid/32 (8 rows). 32-row tile.
// ---------------------------------------------------------------------------
__global__ __launch_bounds__(128) void gemm1_kernel(
    const float* __restrict__ W1,  // [64,128] (this layer)
    const float* __restrict__ b1,  // [128]
    const float* __restrict__ epsp, int n)
{
    __shared__ float Ws[64 * 128];  // 32 KB
    __shared__ float Zs[32 * 64];   // 8 KB (reused for stats reduction)
    int tid = threadIdx.x;

    for (int i = tid; i < 2048; i += 128)
        ((float4*)Ws)[i] = ((const float4*)W1)[i];

    float epsv = 1.0f + __ldg(epsp);
    int r0 = blockIdx.x * 32;
    for (int i = tid; i < 512; i += 128) {   // 32*64/4 float4
        int rr = i >> 4, cc = i & 15;
        int row = r0 + rr;
        float4 z = make_float4(0.f, 0.f, 0.f, 0.f);
        if (row < n) {
            float4 hv = ((const float4*)g_h)[(size_t)row * 16 + cc];
            float4 av = ((const float4*)g_agg)[(size_t)row * 16 + cc];
            z.x = fmaf(epsv, hv.x, av.x);
            z.y = fmaf(epsv, hv.y, av.y);
            z.z = fmaf(epsv, hv.z, av.z);
            z.w = fmaf(epsv, hv.w, av.w);
        }
        ((float4*)Zs)[i] = z;
    }
    __syncthreads();

    int cg = tid & 31;
    int rg = tid >> 5;
    float4 bias = ((const float4*)b1)[cg];
    float4 acc[8];
#pragma unroll
    for (int r = 0; r < 8; r++) acc[r] = bias;

    for (int k = 0; k < 64; k++) {
        float4 w = ((const float4*)Ws)[k * 32 + cg];
#pragma unroll
        for (int r = 0; r < 8; r++) {
            float z = Zs[(rg * 8 + r) * 64 + k];
            acc[r].x = fmaf(z, w.x, acc[r].x);
            acc[r].y = fmaf(z, w.y, acc[r].y);
            acc[r].z = fmaf(z, w.z, acc[r].z);
            acc[r].w = fmaf(z, w.w, acc[r].w);
        }
    }

    float s[4] = {0.f, 0.f, 0.f, 0.f}, sq[4] = {0.f, 0.f, 0.f, 0.f};
#pragma unroll
    for (int r = 0; r < 8; r++) {
        int row = r0 + rg * 8 + r;
        if (row < n) {
            ((float4*)g_y1)[(size_t)row * 32 + cg] = acc[r];
            s[0] += acc[r].x; sq[0] += acc[r].x * acc[r].x;
            s[1] += acc[r].y; sq[1] += acc[r].y * acc[r].y;
            s[2] += acc[r].z; sq[2] += acc[r].z * acc[r].z;
            s[3] += acc[r].w; sq[3] += acc[r].w * acc[r].w;
        }
    }
    __syncthreads();
    float* red = Zs;  // need 1024 floats, have 2048
#pragma unroll
    for (int i = 0; i < 4; i++) {
        red[rg * 128 + cg * 4 + i] = s[i];
        red[512 + rg * 128 + cg * 4 + i] = sq[i];
    }
    __syncthreads();
    if (tid < 128) {
        float ts = red[tid] + red[128 + tid] + red[256 + tid] + red[384 + tid];
        float tq = red[512 + tid] + red[640 + tid] + red[768 + tid] + red[896 + tid];
        atomicAdd(&g_stats[tid], ts);
        atomicAdd(&g_stats[128 + tid], tq);
    }
}

// ---------------------------------------------------------------------------
// Finalize BN stats -> scale/shift
// ---------------------------------------------------------------------------
__global__ void finalize_kernel(const float* __restrict__ g, const float* __restrict__ b,
                                int C, int statoff, int which, float nInv)
{
    int t = threadIdx.x;
    if (t >= C) return;
    float mean = g_stats[statoff + t] * nInv;
    float var = g_stats[statoff + C + t] * nInv - mean * mean;
    var = fmaxf(var, 0.f);
    float inv = rsqrtf(var + 1e-5f);
    float scale = __ldg(&g[t]) * inv;
    float shift = __ldg(&b[t]) - mean * scale;
    float* out = which ? g_bn2 : g_bn1;
    out[t] = scale;
    out[C + t] = shift;
}

// ---------------------------------------------------------------------------
// GEMM2: t = relu(bn1(y1)) (128) -> y2 = t@W2 + b2 (64) -> g_agg (reuse),
// accumulate BN2 stats. blockDim 128: cg = tid%32 (2 cols), rg = tid/32 (8 rows).
// ---------------------------------------------------------------------------
__global__ __launch_bounds__(128) void gemm2_kernel(
    const float* __restrict__ W2,  // [128,64] (this layer)
    const float* __restrict__ b2,  // [64]
    int n)
{
    __shared__ float Ws[128 * 64];  // 32 KB
    __shared__ float Zs[32 * 128];  // 16 KB (reused for stats reduction)
    int tid = threadIdx.x;

    for (int i = tid; i < 2048; i += 128)
        ((float4*)Ws)[i] = ((const float4*)W2)[i];

    int r0 = blockIdx.x * 32;
    for (int i = tid; i < 1024; i += 128) {  // 32*128/4 float4
        int rr = i >> 5, cc = i & 31;
        int row = r0 + rr;
        float4 z = make_float4(0.f, 0.f, 0.f, 0.f);
        if (row < n) {
            float4 y = ((const float4*)g_y1)[(size_t)row * 32 + cc];
            float4 sc = ((const float4*)g_bn1)[cc];
            float4 sh = ((const float4*)g_bn1)[32 + cc];
            z.x = fmaxf(fmaf(y.x, sc.x, sh.x), 0.f);
            z.y = fmaxf(fmaf(y.y, sc.y, sh.y), 0.f);
            z.z = fmaxf(fmaf(y.z, sc.z, sh.z), 0.f);
            z.w = fmaxf(fmaf(y.w, sc.w, sh.w), 0.f);
        }
        ((float4*)Zs)[i] = z;
    }
    __syncthreads();

    int cg = tid & 31;
    int rg = tid >> 5;
    float2 bias = ((const float2*)b2)[cg];
    float2 acc[8];
#pragma unroll
    for (int r = 0; r < 8; r++) acc[r] = bias;

    for (int k = 0; k < 128; k++) {
        float2 w = ((const float2*)Ws)[k * 32 + cg];
#pragma unroll
        for (int r = 0; r < 8; r++) {
            float z = Zs[(rg * 8 + r) * 128 + k];
            acc[r].x = fmaf(z, w.x, acc[r].x);
            acc[r].y = fmaf(z, w.y, acc[r].y);
        }
    }

    float s[2] = {0.f, 0.f}, sq[2] = {0.f, 0.f};
#pragma unroll
    for (int r = 0; r < 8; r++) {
        int row = r0 + rg * 8 + r;
        if (row < n) {
            ((float2*)g_agg)[(size_t)row * 32 + cg] = acc[r];
            s[0] += acc[r].x; sq[0] += acc[r].x * acc[r].x;
            s[1] += acc[r].y; sq[1] += acc[r].y * acc[r].y;
        }
    }
    __syncthreads();
    float* red = Zs;  // need 512 floats
    red[rg * 64 + cg * 2 + 0] = s[0];
    red[rg * 64 + cg * 2 + 1] = s[1];
    red[256 + rg * 64 + cg * 2 + 0] = sq[0];
    red[256 + rg * 64 + cg * 2 + 1] = sq[1];
    __syncthreads();
    if (tid < 64) {
        float ts = red[tid] + red[64 + tid] + red[128 + tid] + red[192 + tid];
        float tq = red[256 + tid] + red[320 + tid] + red[384 + tid] + red[448 + tid];
        atomicAdd(&g_stats[256 + tid], ts);
        atomicAdd(&g_stats[320 + tid], tq);
    }
}

// ---------------------------------------------------------------------------
// Apply BN2 (+ optional relu). Writes to g_h (intermediate layers) or to
// d_out node region (final layer).
// ---------------------------------------------------------------------------
__global__ __launch_bounds__(256) void bn2_apply_kernel(
    float* __restrict__ nodeout, int n, int dorelu, int tofinal)
{
    int i = blockIdx.x * 256 + threadIdx.x;
    if (i >= n * 16) return;
    int c = i & 15;
    float4 y = ((const float4*)g_agg)[i];
    float4 sc = ((const float4*)g_bn2)[c];
    float4 sh = ((const float4*)g_bn2)[16 + c];
    float4 v;
    v.x = fmaf(y.x, sc.x, sh.x);
    v.y = fmaf(y.y, sc.y, sh.y);
    v.z = fmaf(y.z, sc.z, sh.z);
    v.w = fmaf(y.w, sc.w, sh.w);
    if (dorelu) {
        v.x = fmaxf(v.x, 0.f); v.y = fmaxf(v.y, 0.f);
        v.z = fmaxf(v.z, 0.f); v.w = fmaxf(v.w, 0.f);
    }
    float* out = tofinal ? nodeout : g_h;
    ((float4*)out)[i] = v;
}

// ---------------------------------------------------------------------------
// Graph pooling: sum + count via red atomics, then divide.
// ---------------------------------------------------------------------------
__global__ __launch_bounds__(256) void pool_kernel(
    const float* __restrict__ nodeout, const int* __restrict__ batch,
    float* __restrict__ gout, int n)
{
    int wi = blockIdx.x * 256 + threadIdx.x;
    int nid = wi >> 4;
    if (nid >= n) return;
    int c = wi & 15;
    int b = __ldg(&batch[nid]);
    float4 v = ((const float4*)nodeout)[(size_t)nid * 16 + c];
    red_add_v4(gout + (size_t)b * 64 + c * 4, v);
    if (c == 0) atomicAdd(&g_cnt[b], 1.0f);
}

__global__ __launch_bounds__(256) void divide_kernel(float* __restrict__ gout, int b)
{
    int i = blockIdx.x * 256 + threadIdx.x;
    if (i < b * 64) gout[i] = gout[i] / (g_cnt[i >> 6] + 1e-9f);
}

// ---------------------------------------------------------------------------
// Launch
// ---------------------------------------------------------------------------
extern "C" void kernel_launch(void* const* d_in, const int* in_sizes, int n_in,
                              void* d_out, int out_size)
{
    const float* atom_emb = (const float*)d_in[0];
    const float* bond_emb = (const float*)d_in[1];
    const float* eps      = (const float*)d_in[2];
    const float* W1       = (const float*)d_in[3];
    const float* b1       = (const float*)d_in[4];
    const float* bn1_g    = (const float*)d_in[5];
    const float* bn1_b    = (const float*)d_in[6];
    const float* W2       = (const float*)d_in[7];
    const float* b2       = (const float*)d_in[8];
    const float* bn2_g    = (const float*)d_in[9];
    const float* bn2_b    = (const float*)d_in[10];
    const int* x_feat     = (const int*)d_in[11];
    const int* edge_index = (const int*)d_in[12];
    const int* edge_attr  = (const int*)d_in[13];
    const int* batch      = (const int*)d_in[14];

    int n = in_sizes[11] / 9;
    int e = in_sizes[12] / 2;
    int b = out_size / 64 - n;
    float* nodeout = (float*)d_out;
    float* gout = nodeout + (size_t)n * 64;

    int nodeChunks = n * 16;
    int nodeGrid = (nodeChunks + 255) / 256;
    long long edgeItems = (long long)e * 16;
    int edgeGrid = (int)((edgeItems + 255) / 256);
    float nInv = 1.0f / (float)n;

    atom_kernel<<<nodeGrid, 256>>>(atom_emb, x_feat, n);

    for (int l = 0; l < 4; l++) {
        clear_agg_kernel<<<nodeGrid, 256>>>(nodeChunks);
        clear_stats_kernel<<<1, 384>>>();
        edge_kernel<<<edgeGrid, 256>>>(bond_emb + l * 1536, edge_index, edge_attr, e);
        gemm1_kernel<<<(n + 31) / 32, 128>>>(W1 + l * 64 * 128, b1 + l * 128, eps + l, n);
        finalize_kernel<<<1, 128>>>(bn1_g + l * 128, bn1_b + l * 128, 128, 0, 0, nInv);
        gemm2_kernel<<<(n + 31) / 32, 128>>>(W2 + l * 128 * 64, b2 + l * 64, n);
        finalize_kernel<<<1, 64>>>(bn2_g + l * 64, bn2_b + l * 64, 64, 256, 1, nInv);
        bn2_apply_kernel<<<nodeGrid, 256>>>(nodeout, n, (l != 3) ? 1 : 0, (l == 3) ? 1 : 0);
    }

    int poolClear = (b * 64 + 255) / 256;
    clear_pool_kernel<<<poolClear, 256>>>(gout, b);
    pool_kernel<<<nodeGrid, 256>>>(nodeout, batch, gout, n);
    divide_kernel<<<poolClear, 256>>>(gout, b);
}